// round 14
// baseline (speedup 1.0000x reference)
#include <cuda_runtime.h>
#include <math.h>

#define PS 16
#define NB 32
#define IMGSZ (1024*1024)

__device__ __forceinline__ float clamp01(float x) {
    return fminf(fmaxf(x, 0.0f), 1.0f);
}

// ---------------------------------------------------------------------------
// One CTA = one patch, all 32 batches, float4 everywhere.
// Thread t: c4 = t&3 (16B chunk of a row), slot = t>>2, r = slot&15 (row),
// s4 = slot>>4 (batch phase). v[8] float4 = batches 4k+s4 (32 regs).
//  stats: in-register (sum,sumsq) per float4 -> smem partials (conflict-free)
//         -> PARALLEL finalize: thread (b,j) sums 8 partials + shfl-8
//         -> warp 0 shfl-reduces 32 batch stats and computes the code.
//  apply: CTA-uniform affine from registers, STG.128 streaming stores;
//         blur (rare, uniform) stages 16 batches at a time via union buffer.
// ---------------------------------------------------------------------------
__global__ void __launch_bounds__(256, 4)
fused_kernel(const float* __restrict__ img,
             const float* __restrict__ noise,
             const float* __restrict__ r_strong,
             const float* __restrict__ r_drop,
             const float* __restrict__ r_else,
             const float* __restrict__ bright_f,
             const float* __restrict__ contrast_f,
             const float* __restrict__ slight_f,
             const int*   __restrict__ aug_choice,
             const int*   __restrict__ slight_choice,
             float* __restrict__ out) {
    // union: [0..2080) psum[32][65], [2080..4160) psq[32][65]  (stats)
    //        [0..6400) blur tile [16][16][20]                  (blur only)
    __shared__ float ubuf[6400];
    __shared__ float s_q[NB], s_m[NB];
    __shared__ int   s_code;
    __shared__ float s_al, s_be, s_de;

    const int p    = blockIdx.x;             // patch 0..4095
    const int sy   = p >> 6;
    const int px   = p & 63;
    const int t    = threadIdx.x;
    const int c4   = t & 3;                  // 16B chunk in row
    const int slot = t >> 2;
    const int r    = slot & 15;              // patch row
    const int s4   = slot >> 4;              // batch phase 0..3

    const int gofs = (sy * PS + r) * 1024 + px * PS + c4 * 4;

    // ---- Phase 1: 8 front-batched LDG.128 (batches 4k+s4) ----
    float4 v[8];
#pragma unroll
    for (int k = 0; k < 8; ++k)
        v[k] = *reinterpret_cast<const float4*>(
                   img + (size_t)(4 * k + s4) * IMGSZ + gofs);

    // ---- Phase 2a: in-register partials -> smem (conflict-free) ----
    float* psum = ubuf;
    float* psq  = ubuf + 2080;
#pragma unroll
    for (int k = 0; k < 8; ++k) {
        const int b = 4 * k + s4;
        float s  = (v[k].x + v[k].y) + (v[k].z + v[k].w);
        float ss = fmaf(v[k].x, v[k].x,
                   fmaf(v[k].y, v[k].y,
                   fmaf(v[k].z, v[k].z, v[k].w * v[k].w)));
        psum[b * 65 + r * 4 + c4] = s;
        psq [b * 65 + r * 4 + c4] = ss;
    }
    __syncthreads();

    // ---- Phase 2b: parallel finalize. thread (b=t>>3, j=t&7) ----
    {
        const int b = t >> 3;
        const int j = t & 7;
        float s = 0.f, ss = 0.f;
#pragma unroll
        for (int m = 0; m < 8; ++m) {        // banks: (b + 8j + m) % 32 — distinct
            s  += psum[b * 65 + j * 8 + m];
            ss += psq [b * 65 + j * 8 + m];
        }
#pragma unroll
        for (int off = 4; off >= 1; off >>= 1) {
            s  += __shfl_down_sync(0xffffffffu, s,  off, 8);
            ss += __shfl_down_sync(0xffffffffu, ss, off, 8);
        }
        if (j == 0) {
            float mean = s * (1.0f / 256.0f);
            float var  = (ss - s * s * (1.0f / 256.0f)) * (1.0f / 255.0f); // ddof=1
            var = fmaxf(var, 0.0f);
            float std_ = sqrtf(var);
            float iq   = 1.0f - 2.0f * fabsf(mean - 0.5f);
            s_q[b] = (std_ + iq + var) * (1.0f / 3.0f);
            s_m[b] = mean;
        }
    }
    __syncthreads();

    // ---- Phase 3: warp 0 reduces over batches + computes code ----
    if (t < 32) {
        float q = s_q[t];
        float m = s_m[t];
#pragma unroll
        for (int off = 16; off >= 1; off >>= 1) {
            q += __shfl_down_sync(0xffffffffu, q, off);
            m += __shfl_down_sync(0xffffffffu, m, off);
        }
        if (t == 0) {
            q *= (1.0f / NB);
            m *= (1.0f / NB);

            bool low    = q < 0.7f;
            bool strong = low  && (r_strong[p] < 0.8f);
            bool drop   = low  && (q < 0.3f) && (r_drop[p] < 0.1f);
            bool els    = !low && (r_else[p] < 0.3f);

            int code = 0;
            if (strong) code = aug_choice[p] + 1;      // 1..4
            if (els)    code = slight_choice[p] + 5;   // 5..6
            if (drop)   code = 7;

            float alpha = 1.f, beta = 0.f, delta = 0.f;
            if      (code == 1) beta = 0.1f;
            else if (code == 3) alpha = bright_f[p];
            else if (code == 4) { float cf = contrast_f[p]; alpha = cf; delta = m * (1.0f - cf); }
            else if (code == 5) beta = 0.05f;
            else if (code == 6) alpha = slight_f[p];
            else if (code == 7) alpha = 0.f;

            s_code = code; s_al = alpha; s_be = beta; s_de = delta;
        }
    }
    __syncthreads();

    const int   code = s_code;               // uniform across CTA
    const float al   = s_al;
    const float be   = s_be;
    const float de   = s_de;

    // ---- Phase 4: apply + STG.128 streaming stores ----
    if (code == 2) {
        // blur: stage 16 batches at a time through the union buffer
#pragma unroll
        for (int h = 0; h < 2; ++h) {
            __syncthreads();                 // prior readers done
#pragma unroll
            for (int k = 4 * h; k < 4 * h + 4; ++k) {
                const int bl = (4 * k + s4) - 16 * h;   // 0..15
                *reinterpret_cast<float4*>(ubuf + bl * 320 + r * 20 + c4 * 4) = v[k];
            }
            __syncthreads();
#pragma unroll
            for (int k = 4 * h; k < 4 * h + 4; ++k) {
                const int bl = (4 * k + s4) - 16 * h;
                const float* tb = ubuf + bl * 320;
                float rs[4];
#pragma unroll
                for (int j = 0; j < 4; ++j) {
                    const int cc0 = c4 * 4 + j;
                    float sum = 0.f;
#pragma unroll
                    for (int dy = -1; dy <= 1; ++dy) {
                        const int rr = r + dy;
                        if (rr < 0 || rr >= PS) continue;
#pragma unroll
                        for (int dx = -1; dx <= 1; ++dx) {
                            const int cc = cc0 + dx;
                            if (cc < 0 || cc >= PS) continue;
                            sum += tb[rr * 20 + cc];
                        }
                    }
                    rs[j] = sum * (1.0f / 9.0f);
                }
                __stcs(reinterpret_cast<float4*>(
                           out + (size_t)(4 * k + s4) * IMGSZ + gofs),
                       make_float4(rs[0], rs[1], rs[2], rs[3]));
            }
        }
    } else if (be != 0.0f) {
#pragma unroll
        for (int k0 = 0; k0 < 8; k0 += 4) {
            float4 n[4];
#pragma unroll
            for (int kk = 0; kk < 4; ++kk)
                n[kk] = *reinterpret_cast<const float4*>(
                            noise + (size_t)(4 * (k0 + kk) + s4) * IMGSZ + gofs);
#pragma unroll
            for (int kk = 0; kk < 4; ++kk) {
                const int k = k0 + kk;
                float4 o;
                o.x = clamp01(fmaf(be, n[kk].x, fmaf(al, v[k].x, de)));
                o.y = clamp01(fmaf(be, n[kk].y, fmaf(al, v[k].y, de)));
                o.z = clamp01(fmaf(be, n[kk].z, fmaf(al, v[k].z, de)));
                o.w = clamp01(fmaf(be, n[kk].w, fmaf(al, v[k].w, de)));
                __stcs(reinterpret_cast<float4*>(
                           out + (size_t)(4 * k + s4) * IMGSZ + gofs), o);
            }
        }
    } else {
#pragma unroll
        for (int k = 0; k < 8; ++k) {
            float4 o;
            o.x = clamp01(fmaf(al, v[k].x, de));
            o.y = clamp01(fmaf(al, v[k].y, de));
            o.z = clamp01(fmaf(al, v[k].z, de));
            o.w = clamp01(fmaf(al, v[k].w, de));
            __stcs(reinterpret_cast<float4*>(
                       out + (size_t)(4 * k + s4) * IMGSZ + gofs), o);
        }
    }
}

extern "C" void kernel_launch(void* const* d_in, const int* in_sizes, int n_in,
                              void* d_out, int out_size) {
    const float* img           = (const float*)d_in[0];
    const float* noise         = (const float*)d_in[1];
    const float* r_strong      = (const float*)d_in[2];
    const float* r_drop        = (const float*)d_in[3];
    const float* r_else        = (const float*)d_in[4];
    const float* bright_f      = (const float*)d_in[5];
    const float* contrast_f    = (const float*)d_in[6];
    const float* slight_f      = (const float*)d_in[7];
    const int*   aug_choice    = (const int*)d_in[8];
    const int*   slight_choice = (const int*)d_in[9];
    float* out = (float*)d_out;

    fused_kernel<<<4096, 256>>>(img, noise, r_strong, r_drop, r_else,
                                bright_f, contrast_f, slight_f,
                                aug_choice, slight_choice, out);
}